// round 2
// baseline (speedup 1.0000x reference)
#include <cuda_runtime.h>
#include <cstddef>

// CPnAction: action of CP(3) lattice model.
// phi: (B=1024, S=4096, n=6) fp32; shift: (2, 4096) int32; out: (B,1) fp32.
//
// Per site: angles -> unit complex 4-vector z (7 non-trivial reals, zi[3]==0).
// For 2 shifts: term = |<z, z_sh>|^2. action[b] = -4 * sum_{s,d}(term - 1).
//
// One CTA per batch. z staged in shared memory (7 floats/site, stride 7 ->
// bank-conflict-free since gcd(7,32)=1). Each z computed exactly once.

#define SB   4096      // sites per batch (64*64)
#define NANG 6
#define NT   1024      // threads per CTA
#define NSITE_PER_THREAD (SB / NT)
#define SMEM_BYTES ((SB * 7 + 32) * sizeof(float))   // 114816 B

__device__ __forceinline__ float modred(float x, float period, float invp) {
    // r = x - floor(x/period)*period  (matches jnp.mod to ~1 ulp of reduced val)
    float k = floorf(x * invp);
    return fmaf(-k, period, x);
}

extern "C" __global__ void __launch_bounds__(NT, 1)
cpn_action_kernel(const float* __restrict__ phi,
                  const int*   __restrict__ shift,
                  float*       __restrict__ out)
{
    extern __shared__ float zs[];            // SB*7 floats + 32 for reduction
    float* red = zs + SB * 7;

    const int b   = blockIdx.x;
    const int tid = threadIdx.x;

    const float PI_F     = 3.14159265358979323846f;   // rounds to np.float32(pi)
    const float TWO_PI_F = 6.28318530717958647692f;
    const float INV_PI   = 0.31830988618379067154f;
    const float INV_2PI  = 0.15915494309189533577f;

    const float* pb = phi + (size_t)b * (SB * NANG);

    // ---------------- Phase 1: build z for every site, stage to smem --------
    #pragma unroll
    for (int i = 0; i < NSITE_PER_THREAD; ++i) {
        int s = tid + i * NT;
        // 6 angles per site; 24B stride, base 8B-aligned -> float2 loads legal
        const float2* p2 = reinterpret_cast<const float2*>(pb + (size_t)s * NANG);
        float2 v0 = p2[0], v1 = p2[1], v2 = p2[2];

        float a0 = modred(v0.x, PI_F, INV_PI);
        float a1 = modred(v0.y, PI_F, INV_PI);
        float a2 = modred(v1.x, PI_F, INV_PI);
        float a3 = modred(v1.y, PI_F, INV_PI);
        float a4 = modred(v2.x, PI_F, INV_PI);
        float a5 = modred(v2.y, TWO_PI_F, INV_2PI);

        float s0, c0, s1, c1, s2, c2, s3, c3, s4, c4, s5, c5;
        __sincosf(a0, &s0, &c0);
        __sincosf(a1, &s1, &c1);
        __sincosf(a2, &s2, &c2);
        __sincosf(a3, &s3, &c3);
        __sincosf(a4, &s4, &c4);
        __sincosf(a5, &s5, &c5);

        // cumprod of sines and hyperspherical components
        float S0 = s0;
        float S1 = S0 * s1;
        float S2 = S1 * s2;
        float S3 = S2 * s3;
        float S4 = S3 * s4;
        float S5 = S4 * s5;

        float* zp = zs + s * 7;
        zp[0] = c0;          // zr0
        zp[1] = c1 * S0;     // zr1
        zp[2] = c2 * S1;     // zr2
        zp[3] = c3 * S2;     // zr3
        zp[4] = c4 * S3;     // zi0
        zp[5] = c5 * S4;     // zi1
        zp[6] = S5;          // zi2   (zi3 == 0 implicitly)
    }

    __syncthreads();

    // ---------------- Phase 2: link terms ----------------------------------
    float acc = 0.0f;   // sum of (dre^2 + dim^2); constant -8192 folded at end

    #pragma unroll
    for (int i = 0; i < NSITE_PER_THREAD; ++i) {
        int s = tid + i * NT;
        int n0 = shift[s];
        int n1 = shift[SB + s];

        const float* zp = zs + s * 7;
        const float* q0 = zs + n0 * 7;
        const float* q1 = zs + n1 * 7;

        float x0 = zp[0], x1 = zp[1], x2 = zp[2], x3 = zp[3];
        float x4 = zp[4], x5 = zp[5], x6 = zp[6];

        // neighbor 0
        {
            float y0 = q0[0], y1 = q0[1], y2 = q0[2], y3 = q0[3];
            float y4 = q0[4], y5 = q0[5], y6 = q0[6];

            float dre = x0 * y0;
            dre = fmaf(x1, y1, dre);
            dre = fmaf(x2, y2, dre);
            dre = fmaf(x3, y3, dre);
            dre = fmaf(-x4, y4, dre);
            dre = fmaf(-x5, y5, dre);
            dre = fmaf(-x6, y6, dre);

            float dim = x0 * y4;
            dim = fmaf(x1, y5, dim);
            dim = fmaf(x2, y6, dim);
            dim = fmaf(x4, y0, dim);
            dim = fmaf(x5, y1, dim);
            dim = fmaf(x6, y2, dim);

            acc = fmaf(dre, dre, acc);
            acc = fmaf(dim, dim, acc);
        }
        // neighbor 1
        {
            float y0 = q1[0], y1 = q1[1], y2 = q1[2], y3 = q1[3];
            float y4 = q1[4], y5 = q1[5], y6 = q1[6];

            float dre = x0 * y0;
            dre = fmaf(x1, y1, dre);
            dre = fmaf(x2, y2, dre);
            dre = fmaf(x3, y3, dre);
            dre = fmaf(-x4, y4, dre);
            dre = fmaf(-x5, y5, dre);
            dre = fmaf(-x6, y6, dre);

            float dim = x0 * y4;
            dim = fmaf(x1, y5, dim);
            dim = fmaf(x2, y6, dim);
            dim = fmaf(x4, y0, dim);
            dim = fmaf(x5, y1, dim);
            dim = fmaf(x6, y2, dim);

            acc = fmaf(dre, dre, acc);
            acc = fmaf(dim, dim, acc);
        }
    }

    // ---------------- Reduction --------------------------------------------
    #pragma unroll
    for (int off = 16; off > 0; off >>= 1)
        acc += __shfl_xor_sync(0xFFFFFFFFu, acc, off);

    int wid  = tid >> 5;
    int lane = tid & 31;
    if (lane == 0) red[wid] = acc;
    __syncthreads();

    if (wid == 0) {
        float v = red[lane];          // NT/32 == 32 warps exactly
        #pragma unroll
        for (int off = 16; off > 0; off >>= 1)
            v += __shfl_xor_sync(0xFFFFFFFFu, v, off);
        if (lane == 0) {
            // action = -N*BETA * sum(term - 1),  N = (n+1+1)/2 = 4, 2*SB terms
            out[b] = -4.0f * (v - 2.0f * (float)SB);
        }
    }
}

extern "C" void kernel_launch(void* const* d_in, const int* in_sizes, int n_in,
                              void* d_out, int out_size)
{
    const float* phi   = (const float*)d_in[0];
    const int*   shift = (const int*)d_in[1];
    float*       out   = (float*)d_out;

    int B = out_size > 0 ? out_size : in_sizes[0] / (SB * NANG);   // 1024

    // Opt-in to >48KB dynamic smem. Idempotent; capture-safe (non-stream API).
    (void)cudaFuncSetAttribute(cpn_action_kernel,
                               cudaFuncAttributeMaxDynamicSharedMemorySize,
                               (int)SMEM_BYTES);

    cpn_action_kernel<<<B, NT, (int)SMEM_BYTES>>>(phi, shift, out);
}

// round 3
// speedup vs baseline: 1.1119x; 1.1119x over previous
#include <cuda_runtime.h>
#include <cstddef>

// CPnAction: action of CP(3) lattice model.
// phi: (B=1024, S=4096, n=6) fp32; shift: (2, 4096) int32; out: (B,1) fp32.
//
// One CTA per batch, NT=512, 2 CTAs co-resident per SM (smem 112KB each,
// regs capped at 64 via launch_bounds). z staged in smem, 7 floats/site,
// stride 7 -> conflict-free (gcd(7,32)=1).

#define SB   4096      // sites per batch (64*64)
#define NANG 6
#define NT   512       // threads per CTA
#define SPT  (SB / NT) // 8 sites per thread
#define NWARP (NT / 32)
#define SMEM_FLOATS (SB * 7 + NWARP)
#define SMEM_BYTES  (SMEM_FLOATS * sizeof(float))   // 114752 B

__device__ __forceinline__ float modred(float x, float period, float invp) {
    // r = x - floor(x/period)*period  (matches jnp.mod to ~1 ulp of reduced val)
    float k = floorf(x * invp);
    return fmaf(-k, period, x);
}

extern "C" __global__ void __launch_bounds__(NT, 2)
cpn_action_kernel(const float* __restrict__ phi,
                  const int*   __restrict__ shift,
                  float*       __restrict__ out)
{
    extern __shared__ float zs[];            // SB*7 floats + NWARP for reduction
    float* red = zs + SB * 7;

    const int b   = blockIdx.x;
    const int tid = threadIdx.x;

    const float PI_F     = 3.14159265358979323846f;
    const float TWO_PI_F = 6.28318530717958647692f;
    const float INV_PI   = 0.31830988618379067154f;
    const float INV_2PI  = 0.15915494309189533577f;

    const float* pb = phi + (size_t)b * (SB * NANG);

    // ---------------- Phase 1: build z for every site, stage to smem --------
    // Two batches of 4 sites: front-load all 12 LDG.64 per batch for MLP.
    #pragma unroll
    for (int batch = 0; batch < SPT / 4; ++batch) {
        float2 v[4][3];
        #pragma unroll
        for (int j = 0; j < 4; ++j) {
            int s = tid + (batch * 4 + j) * NT;
            const float2* p2 = reinterpret_cast<const float2*>(pb + (size_t)s * NANG);
            v[j][0] = p2[0];
            v[j][1] = p2[1];
            v[j][2] = p2[2];
        }

        #pragma unroll
        for (int j = 0; j < 4; ++j) {
            int s = tid + (batch * 4 + j) * NT;

            float a0 = modred(v[j][0].x, PI_F, INV_PI);
            float a1 = modred(v[j][0].y, PI_F, INV_PI);
            float a2 = modred(v[j][1].x, PI_F, INV_PI);
            float a3 = modred(v[j][1].y, PI_F, INV_PI);
            float a4 = modred(v[j][2].x, PI_F, INV_PI);
            float a5 = modred(v[j][2].y, TWO_PI_F, INV_2PI);

            float s0, c0, s1, c1, s2, c2, s3, c3, s4, c4, s5, c5;
            __sincosf(a0, &s0, &c0);
            __sincosf(a1, &s1, &c1);
            __sincosf(a2, &s2, &c2);
            __sincosf(a3, &s3, &c3);
            __sincosf(a4, &s4, &c4);
            __sincosf(a5, &s5, &c5);

            float S0 = s0;
            float S1 = S0 * s1;
            float S2 = S1 * s2;
            float S3 = S2 * s3;
            float S4 = S3 * s4;
            float S5 = S4 * s5;

            float* zp = zs + s * 7;
            zp[0] = c0;          // zr0
            zp[1] = c1 * S0;     // zr1
            zp[2] = c2 * S1;     // zr2
            zp[3] = c3 * S2;     // zr3
            zp[4] = c4 * S3;     // zi0
            zp[5] = c5 * S4;     // zi1
            zp[6] = S5;          // zi2   (zi3 == 0 implicitly)
        }
    }

    __syncthreads();

    // ---------------- Phase 2: link terms ----------------------------------
    float acc = 0.0f;   // sum of (dre^2 + dim^2); constant folded at end

    #pragma unroll
    for (int i = 0; i < SPT; ++i) {
        int s = tid + i * NT;
        int n0 = shift[s];
        int n1 = shift[SB + s];

        const float* zp = zs + s * 7;
        const float* q0 = zs + n0 * 7;
        const float* q1 = zs + n1 * 7;

        float x0 = zp[0], x1 = zp[1], x2 = zp[2], x3 = zp[3];
        float x4 = zp[4], x5 = zp[5], x6 = zp[6];

        // neighbor 0
        {
            float y0 = q0[0], y1 = q0[1], y2 = q0[2], y3 = q0[3];
            float y4 = q0[4], y5 = q0[5], y6 = q0[6];

            float dre = x0 * y0;
            dre = fmaf(x1, y1, dre);
            dre = fmaf(x2, y2, dre);
            dre = fmaf(x3, y3, dre);
            dre = fmaf(-x4, y4, dre);
            dre = fmaf(-x5, y5, dre);
            dre = fmaf(-x6, y6, dre);

            float dim = x0 * y4;
            dim = fmaf(x1, y5, dim);
            dim = fmaf(x2, y6, dim);
            dim = fmaf(x4, y0, dim);
            dim = fmaf(x5, y1, dim);
            dim = fmaf(x6, y2, dim);

            acc = fmaf(dre, dre, acc);
            acc = fmaf(dim, dim, acc);
        }
        // neighbor 1
        {
            float y0 = q1[0], y1 = q1[1], y2 = q1[2], y3 = q1[3];
            float y4 = q1[4], y5 = q1[5], y6 = q1[6];

            float dre = x0 * y0;
            dre = fmaf(x1, y1, dre);
            dre = fmaf(x2, y2, dre);
            dre = fmaf(x3, y3, dre);
            dre = fmaf(-x4, y4, dre);
            dre = fmaf(-x5, y5, dre);
            dre = fmaf(-x6, y6, dre);

            float dim = x0 * y4;
            dim = fmaf(x1, y5, dim);
            dim = fmaf(x2, y6, dim);
            dim = fmaf(x4, y0, dim);
            dim = fmaf(x5, y1, dim);
            dim = fmaf(x6, y2, dim);

            acc = fmaf(dre, dre, acc);
            acc = fmaf(dim, dim, acc);
        }
    }

    // ---------------- Reduction --------------------------------------------
    #pragma unroll
    for (int off = 16; off > 0; off >>= 1)
        acc += __shfl_xor_sync(0xFFFFFFFFu, acc, off);

    int wid  = tid >> 5;
    int lane = tid & 31;
    if (lane == 0) red[wid] = acc;
    __syncthreads();

    if (wid == 0) {
        float v = (lane < NWARP) ? red[lane] : 0.0f;
        #pragma unroll
        for (int off = NWARP / 2; off > 0; off >>= 1)
            v += __shfl_xor_sync(0xFFFFFFFFu, v, off);
        if (lane == 0) {
            // action = -N*BETA * sum(term - 1),  N = 4, 2*SB terms
            out[b] = -4.0f * (v - 2.0f * (float)SB);
        }
    }
}

extern "C" void kernel_launch(void* const* d_in, const int* in_sizes, int n_in,
                              void* d_out, int out_size)
{
    const float* phi   = (const float*)d_in[0];
    const int*   shift = (const int*)d_in[1];
    float*       out   = (float*)d_out;

    int B = out_size > 0 ? out_size : in_sizes[0] / (SB * NANG);   // 1024

    (void)cudaFuncSetAttribute(cpn_action_kernel,
                               cudaFuncAttributeMaxDynamicSharedMemorySize,
                               (int)SMEM_BYTES);

    cpn_action_kernel<<<B, NT, (int)SMEM_BYTES>>>(phi, shift, out);
}

// round 4
// speedup vs baseline: 1.4576x; 1.3110x over previous
#include <cuda_runtime.h>
#include <cuda_fp16.h>
#include <cstddef>

// CPnAction: action of CP(3) lattice model.
// phi: (B=1024, S=4096, n=6) fp32; shift: (2, 4096) int32; out: (B,1) fp32.
//
// One CTA per batch, NT=256, 3 CTAs co-resident per SM.
// z staged in smem as 8 fp16 packed in one uint4 per site (64KB/CTA):
//   h0=zr0 h1=zr1 h2=zr2 h3=zr3 h4=zi0 h5=zi1 h6=zi2 h7=0
// Phase 2 reads each z with a single conflict-free LDS.128.

#define SB   4096      // sites per batch (64*64)
#define NANG 6
#define NT   256       // threads per CTA
#define SPT  (SB / NT) // 16 sites per thread
#define NWARP (NT / 32)
#define SMEM_BYTES (SB * 16 + NWARP * 4)   // 65568 B

__device__ __forceinline__ float modred(float x, float period, float invp) {
    float k = floorf(x * invp);
    return fmaf(-k, period, x);
}

struct Z7 { float v[7]; };

__device__ __forceinline__ Z7 unpack_z(uint4 u) {
    __half2* h = reinterpret_cast<__half2*>(&u);
    float2 a = __half22float2(h[0]);
    float2 b = __half22float2(h[1]);
    float2 c = __half22float2(h[2]);
    float2 d = __half22float2(h[3]);
    Z7 z;
    z.v[0] = a.x; z.v[1] = a.y; z.v[2] = b.x; z.v[3] = b.y;
    z.v[4] = c.x; z.v[5] = c.y; z.v[6] = d.x;
    return z;
}

extern "C" __global__ void __launch_bounds__(NT, 3)
cpn_action_kernel(const float* __restrict__ phi,
                  const int*   __restrict__ shift,
                  float*       __restrict__ out)
{
    extern __shared__ uint4 zsu[];             // SB uint4 + NWARP floats
    float* red = reinterpret_cast<float*>(zsu + SB);

    const int b   = blockIdx.x;
    const int tid = threadIdx.x;

    const float PI_F     = 3.14159265358979323846f;
    const float TWO_PI_F = 6.28318530717958647692f;
    const float INV_PI   = 0.31830988618379067154f;
    const float INV_2PI  = 0.15915494309189533577f;

    const float* pb = phi + (size_t)b * (SB * NANG);

    // ---------------- Phase 1: build z for every site, stage to smem --------
    #pragma unroll
    for (int batch = 0; batch < SPT / 4; ++batch) {
        float2 v[4][3];
        #pragma unroll
        for (int j = 0; j < 4; ++j) {
            int s = tid + (batch * 4 + j) * NT;
            const float2* p2 = reinterpret_cast<const float2*>(pb + (size_t)s * NANG);
            v[j][0] = p2[0];
            v[j][1] = p2[1];
            v[j][2] = p2[2];
        }

        #pragma unroll
        for (int j = 0; j < 4; ++j) {
            int s = tid + (batch * 4 + j) * NT;

            float a0 = modred(v[j][0].x, PI_F, INV_PI);
            float a1 = modred(v[j][0].y, PI_F, INV_PI);
            float a2 = modred(v[j][1].x, PI_F, INV_PI);
            float a3 = modred(v[j][1].y, PI_F, INV_PI);
            float a4 = modred(v[j][2].x, PI_F, INV_PI);
            float a5 = modred(v[j][2].y, TWO_PI_F, INV_2PI);

            float s0, c0, s1, c1, s2, c2, s3, c3, s4, c4, s5, c5;
            __sincosf(a0, &s0, &c0);
            __sincosf(a1, &s1, &c1);
            __sincosf(a2, &s2, &c2);
            __sincosf(a3, &s3, &c3);
            __sincosf(a4, &s4, &c4);
            __sincosf(a5, &s5, &c5);

            float S0 = s0;
            float S1 = S0 * s1;
            float S2 = S1 * s2;
            float S3 = S2 * s3;
            float S4 = S3 * s4;
            float S5 = S4 * s5;

            float zr0 = c0;
            float zr1 = c1 * S0;
            float zr2 = c2 * S1;
            float zr3 = c3 * S2;
            float zi0 = c4 * S3;
            float zi1 = c5 * S4;
            float zi2 = S5;

            __half2 h0 = __floats2half2_rn(zr0, zr1);
            __half2 h1 = __floats2half2_rn(zr2, zr3);
            __half2 h2 = __floats2half2_rn(zi0, zi1);
            __half2 h3 = __floats2half2_rn(zi2, 0.0f);

            uint4 u;
            u.x = *reinterpret_cast<unsigned*>(&h0);
            u.y = *reinterpret_cast<unsigned*>(&h1);
            u.z = *reinterpret_cast<unsigned*>(&h2);
            u.w = *reinterpret_cast<unsigned*>(&h3);
            zsu[s] = u;                       // one STS.128
        }
    }

    __syncthreads();

    // ---------------- Phase 2: link terms ----------------------------------
    float acc = 0.0f;   // sum of (dre^2 + dim^2); constant folded at end

    #pragma unroll 4
    for (int i = 0; i < SPT; ++i) {
        int s = tid + i * NT;
        int n0 = shift[s];
        int n1 = shift[SB + s];

        uint4 us  = zsu[s];                   // LDS.128, conflict-free
        uint4 u0  = zsu[n0];
        uint4 u1  = zsu[n1];

        Z7 x  = unpack_z(us);
        Z7 y0 = unpack_z(u0);
        Z7 y1 = unpack_z(u1);

        // neighbor 0
        {
            float dre = x.v[0] * y0.v[0];
            dre = fmaf(x.v[1], y0.v[1], dre);
            dre = fmaf(x.v[2], y0.v[2], dre);
            dre = fmaf(x.v[3], y0.v[3], dre);
            dre = fmaf(-x.v[4], y0.v[4], dre);
            dre = fmaf(-x.v[5], y0.v[5], dre);
            dre = fmaf(-x.v[6], y0.v[6], dre);

            float dim = x.v[0] * y0.v[4];
            dim = fmaf(x.v[1], y0.v[5], dim);
            dim = fmaf(x.v[2], y0.v[6], dim);
            dim = fmaf(x.v[4], y0.v[0], dim);
            dim = fmaf(x.v[5], y0.v[1], dim);
            dim = fmaf(x.v[6], y0.v[2], dim);

            acc = fmaf(dre, dre, acc);
            acc = fmaf(dim, dim, acc);
        }
        // neighbor 1
        {
            float dre = x.v[0] * y1.v[0];
            dre = fmaf(x.v[1], y1.v[1], dre);
            dre = fmaf(x.v[2], y1.v[2], dre);
            dre = fmaf(x.v[3], y1.v[3], dre);
            dre = fmaf(-x.v[4], y1.v[4], dre);
            dre = fmaf(-x.v[5], y1.v[5], dre);
            dre = fmaf(-x.v[6], y1.v[6], dre);

            float dim = x.v[0] * y1.v[4];
            dim = fmaf(x.v[1], y1.v[5], dim);
            dim = fmaf(x.v[2], y1.v[6], dim);
            dim = fmaf(x.v[4], y1.v[0], dim);
            dim = fmaf(x.v[5], y1.v[1], dim);
            dim = fmaf(x.v[6], y1.v[2], dim);

            acc = fmaf(dre, dre, acc);
            acc = fmaf(dim, dim, acc);
        }
    }

    // ---------------- Reduction --------------------------------------------
    #pragma unroll
    for (int off = 16; off > 0; off >>= 1)
        acc += __shfl_xor_sync(0xFFFFFFFFu, acc, off);

    int wid  = tid >> 5;
    int lane = tid & 31;
    if (lane == 0) red[wid] = acc;
    __syncthreads();

    if (wid == 0) {
        float v = (lane < NWARP) ? red[lane] : 0.0f;
        #pragma unroll
        for (int off = NWARP / 2; off > 0; off >>= 1)
            v += __shfl_xor_sync(0xFFFFFFFFu, v, off);
        if (lane == 0) {
            // action = -N*BETA * sum(term - 1),  N = 4, 2*SB terms
            out[b] = -4.0f * (v - 2.0f * (float)SB);
        }
    }
}

extern "C" void kernel_launch(void* const* d_in, const int* in_sizes, int n_in,
                              void* d_out, int out_size)
{
    const float* phi   = (const float*)d_in[0];
    const int*   shift = (const int*)d_in[1];
    float*       out   = (float*)d_out;

    int B = out_size > 0 ? out_size : in_sizes[0] / (SB * NANG);   // 1024

    (void)cudaFuncSetAttribute(cpn_action_kernel,
                               cudaFuncAttributeMaxDynamicSharedMemorySize,
                               (int)SMEM_BYTES);

    cpn_action_kernel<<<B, NT, (int)SMEM_BYTES>>>(phi, shift, out);
}

// round 5
// speedup vs baseline: 1.5713x; 1.0780x over previous
#include <cuda_runtime.h>
#include <cuda_fp16.h>
#include <cstddef>

// CPnAction: action of CP(3) lattice model.
// phi: (B=1024, S=4096, n=6) fp32; shift: (2, 4096) int32; out: (B,1) fp32.
//
// One CTA per batch, NT=512, 3 CTAs co-resident per SM (48 warps, regs<=42
// via launch_bounds). z staged in smem as 8 fp16 in one uint4 per site:
//   u.x=[zr0,zr1] u.y=[zr2,zr3] u.z=[zi0,zi1] u.w=[zi2,0]
// Phase 2: dot products computed directly in half2 (HFMA2), fp32 squares/acc.

#define SB   4096      // sites per batch (64*64)
#define NANG 6
#define NT   512       // threads per CTA
#define SPT  (SB / NT) // 8 sites per thread
#define NWARP (NT / 32)
#define SMEM_BYTES (SB * 16 + NWARP * 4)   // 65600 B

__device__ __forceinline__ float modred(float x, float period, float invp) {
    float k = floorf(x * invp);
    return fmaf(-k, period, x);
}

// |<x, y>|^2 contribution from packed half2 z-vectors.
__device__ __forceinline__ float link_term(uint4 xu, uint4 yu) {
    const __half2* x = reinterpret_cast<const __half2*>(&xu);
    const __half2* y = reinterpret_cast<const __half2*>(&yu);

    // dre = zr.zr' - zi.zi'
    __half2 a = __hfma2(x[1], y[1], __hmul2(x[0], y[0]));   // zr pairs
    __half2 bb = __hfma2(x[3], y[3], __hmul2(x[2], y[2]));  // zi pairs (pad*pad=0)
    // dim = zr.zi' + zi.zr'   (zr3 pairs with pad 0, pad pairs with yr3 -> 0)
    __half2 dd = __hmul2(x[0], y[2]);
    dd = __hfma2(x[1], y[3], dd);
    dd = __hfma2(x[2], y[0], dd);
    dd = __hfma2(x[3], y[1], dd);

    float2 af = __half22float2(a);
    float2 bf = __half22float2(bb);
    float2 df = __half22float2(dd);
    float dre = (af.x + af.y) - (bf.x + bf.y);
    float dim = df.x + df.y;
    return fmaf(dre, dre, dim * dim);
}

extern "C" __global__ void __launch_bounds__(NT, 3)
cpn_action_kernel(const float* __restrict__ phi,
                  const int*   __restrict__ shift,
                  float*       __restrict__ out)
{
    extern __shared__ uint4 zsu[];             // SB uint4 + NWARP floats
    float* red = reinterpret_cast<float*>(zsu + SB);

    const int b   = blockIdx.x;
    const int tid = threadIdx.x;

    const float PI_F     = 3.14159265358979323846f;
    const float TWO_PI_F = 6.28318530717958647692f;
    const float INV_PI   = 0.31830988618379067154f;
    const float INV_2PI  = 0.15915494309189533577f;

    const float* pb = phi + (size_t)b * (SB * NANG);

    // ---------------- Phase 1: build z for every site, stage to smem --------
    // Batches of 2 sites (6 LDG.64 in flight) to keep register pressure low.
    #pragma unroll
    for (int batch = 0; batch < SPT / 2; ++batch) {
        float2 v[2][3];
        #pragma unroll
        for (int j = 0; j < 2; ++j) {
            int s = tid + (batch * 2 + j) * NT;
            const float2* p2 = reinterpret_cast<const float2*>(pb + (size_t)s * NANG);
            v[j][0] = p2[0];
            v[j][1] = p2[1];
            v[j][2] = p2[2];
        }

        #pragma unroll
        for (int j = 0; j < 2; ++j) {
            int s = tid + (batch * 2 + j) * NT;

            float a0 = modred(v[j][0].x, PI_F, INV_PI);
            float a1 = modred(v[j][0].y, PI_F, INV_PI);
            float a2 = modred(v[j][1].x, PI_F, INV_PI);
            float a3 = modred(v[j][1].y, PI_F, INV_PI);
            float a4 = modred(v[j][2].x, PI_F, INV_PI);
            float a5 = modred(v[j][2].y, TWO_PI_F, INV_2PI);

            float s0, c0, s1, c1, s2, c2, s3, c3, s4, c4, s5, c5;
            __sincosf(a0, &s0, &c0);
            __sincosf(a1, &s1, &c1);
            __sincosf(a2, &s2, &c2);
            __sincosf(a3, &s3, &c3);
            __sincosf(a4, &s4, &c4);
            __sincosf(a5, &s5, &c5);

            float S0 = s0;
            float S1 = S0 * s1;
            float S2 = S1 * s2;
            float S3 = S2 * s3;
            float S4 = S3 * s4;
            float S5 = S4 * s5;

            __half2 h0 = __floats2half2_rn(c0,      c1 * S0);
            __half2 h1 = __floats2half2_rn(c2 * S1, c3 * S2);
            __half2 h2 = __floats2half2_rn(c4 * S3, c5 * S4);
            __half2 h3 = __floats2half2_rn(S5,      0.0f);

            uint4 u;
            u.x = *reinterpret_cast<unsigned*>(&h0);
            u.y = *reinterpret_cast<unsigned*>(&h1);
            u.z = *reinterpret_cast<unsigned*>(&h2);
            u.w = *reinterpret_cast<unsigned*>(&h3);
            zsu[s] = u;                       // one STS.128
        }
    }

    __syncthreads();

    // ---------------- Phase 2: link terms ----------------------------------
    float acc = 0.0f;   // sum of (dre^2 + dim^2); constant folded at end

    #pragma unroll 2
    for (int i = 0; i < SPT; ++i) {
        int s = tid + i * NT;
        int n0 = shift[s];
        int n1 = shift[SB + s];

        uint4 us = zsu[s];                    // LDS.128, conflict-free
        uint4 u0 = zsu[n0];
        uint4 u1 = zsu[n1];

        acc += link_term(us, u0);
        acc += link_term(us, u1);
    }

    // ---------------- Reduction --------------------------------------------
    #pragma unroll
    for (int off = 16; off > 0; off >>= 1)
        acc += __shfl_xor_sync(0xFFFFFFFFu, acc, off);

    int wid  = tid >> 5;
    int lane = tid & 31;
    if (lane == 0) red[wid] = acc;
    __syncthreads();

    if (wid == 0) {
        float v = (lane < NWARP) ? red[lane] : 0.0f;
        #pragma unroll
        for (int off = NWARP / 2; off > 0; off >>= 1)
            v += __shfl_xor_sync(0xFFFFFFFFu, v, off);
        if (lane == 0) {
            // action = -N*BETA * sum(term - 1),  N = 4, 2*SB terms
            out[b] = -4.0f * (v - 2.0f * (float)SB);
        }
    }
}

extern "C" void kernel_launch(void* const* d_in, const int* in_sizes, int n_in,
                              void* d_out, int out_size)
{
    const float* phi   = (const float*)d_in[0];
    const int*   shift = (const int*)d_in[1];
    float*       out   = (float*)d_out;

    int B = out_size > 0 ? out_size : in_sizes[0] / (SB * NANG);   // 1024

    (void)cudaFuncSetAttribute(cpn_action_kernel,
                               cudaFuncAttributeMaxDynamicSharedMemorySize,
                               (int)SMEM_BYTES);

    cpn_action_kernel<<<B, NT, (int)SMEM_BYTES>>>(phi, shift, out);
}